// round 8
// baseline (speedup 1.0000x reference)
#include <cuda_runtime.h>
#include <cstdint>

// ITA integer softmax (WIDTH=16, BITS=8, EPS_MAX=1.0 -> all float-shift
// computations in the reference reduce to exact integer differences).
//
// OUTPUT DTYPE: the harness promotes the reference's uint8 result to
// float32 (only f32/i32/bf16 are supported dtypes). Each result value
// (0..255 integer) is written as a float32 element.
//
// One warp = one row (K=2048 = 128 groups of 16). Lane l owns groups
// g = 32k + l (k=0..3): 64 elements held in registers between phases.
//
// Phases (per 8-row block):
//   1) load row: 16x LDG.128 per lane; per-group cmax -> smem
//   2) serial prefix-max over 128 groups (8 rows SIMD in warp 0) -> gpre, gmax
//   3) per-group t_g = sum(256 >> d), d = gpre_g - v  (parallel) -> smem
//   4) serial eps scan: e = (e >> s_g) + t_g ; inv = 65280 / e  (warp 0 SIMD)
//   5) output: float(inv >> (gmax - v)), 16x STG.128 (float4) per lane,
//      each lane writing contiguous 64B chunks (sector-aligned).

#define RPB 8           // rows per block (8 warps)
#define GPAD 132        // 128 groups + 4 pad: lane stride 132 -> conflict-free

__global__ __launch_bounds__(256)
void ita_softmax_kernel(const int* __restrict__ x,
                        float* __restrict__ out,
                        int rows)
{
    const int warp = threadIdx.x >> 5;
    const int lane = threadIdx.x & 31;

    __shared__ int s_cmax[RPB][GPAD];
    __shared__ int s_gpre[RPB][GPAD];
    __shared__ int s_t[RPB][GPAD];
    __shared__ int s_inv[RPB];
    __shared__ int s_gmax[RPB];

    for (int row0 = blockIdx.x * RPB; row0 < rows; row0 += gridDim.x * RPB) {
        const int row = row0 + warp;
        const bool valid = (row < rows);

        int v[4][16];

        // ---- Phase 1: load + per-group max ----
        if (valid) {
            const int4* xrow = reinterpret_cast<const int4*>(x) + (size_t)row * 512;
            #pragma unroll
            for (int k = 0; k < 4; k++) {
                const int g = k * 32 + lane;       // group index 0..127
                #pragma unroll
                for (int j = 0; j < 4; j++) {
                    int4 t4 = xrow[g * 4 + j];
                    v[k][j * 4 + 0] = t4.x;
                    v[k][j * 4 + 1] = t4.y;
                    v[k][j * 4 + 2] = t4.z;
                    v[k][j * 4 + 3] = t4.w;
                }
                int cm = v[k][0];
                #pragma unroll
                for (int j = 1; j < 16; j++) cm = (v[k][j] > cm) ? v[k][j] : cm;
                s_cmax[warp][g] = cm;
            }
        }
        __syncthreads();

        // ---- Phase 2: serial prefix max over groups (8 rows SIMD) ----
        if (warp == 0 && lane < RPB) {
            const int* cm = s_cmax[lane];
            int* gp = s_gpre[lane];
            int g_ = -128;
            #pragma unroll 8
            for (int g = 0; g < 128; g++) {
                int c = cm[g];
                if (c > g_) g_ = c;
                gp[g] = g_;
            }
            s_gmax[lane] = g_;
        }
        __syncthreads();

        // ---- Phase 3: per-group exp sums t_g ----
        if (valid) {
            #pragma unroll
            for (int k = 0; k < 4; k++) {
                const int g = k * 32 + lane;
                const int pm = s_gpre[warp][g];
                int t = 0;
                #pragma unroll
                for (int j = 0; j < 16; j++) {
                    int d = pm - v[k][j];          // >= 0
                    t += (d < 9) ? (256 >> d) : 0; // d>=9 contributes 0 (ref)
                }
                s_t[warp][g] = t;
            }
        }
        __syncthreads();

        // ---- Phase 4: serial eps scan + reciprocal (8 rows SIMD) ----
        if (warp == 0 && lane < RPB) {
            const int* gp = s_gpre[lane];
            const int* tt = s_t[lane];
            int prev = -128;
            int e = 0;
            #pragma unroll 8
            for (int g = 0; g < 128; g++) {
                int gm_ = gp[g];
                int s = gm_ - prev;                // >= 0
                prev = gm_;
                e = ((s < 32) ? (e >> s) : 0) + tt[g];
            }
            s_inv[lane] = 65280 / e;               // e >= 256 always
        }
        __syncthreads();

        // ---- Phase 5: output as float32 ----
        if (valid) {
            const int inv = s_inv[warp];           // <= 255
            const int gm = s_gmax[warp];
            float4* orow = reinterpret_cast<float4*>(out + (size_t)row * 2048);
            #pragma unroll
            for (int k = 0; k < 4; k++) {
                const int g = k * 32 + lane;
                #pragma unroll
                for (int j = 0; j < 4; j++) {
                    int d0 = gm - v[k][j * 4 + 0];
                    int d1 = gm - v[k][j * 4 + 1];
                    int d2 = gm - v[k][j * 4 + 2];
                    int d3 = gm - v[k][j * 4 + 3];
                    float4 f;
                    f.x = (float)((d0 < 32) ? ((unsigned)inv >> d0) : 0u);
                    f.y = (float)((d1 < 32) ? ((unsigned)inv >> d1) : 0u);
                    f.z = (float)((d2 < 32) ? ((unsigned)inv >> d2) : 0u);
                    f.w = (float)((d3 < 32) ? ((unsigned)inv >> d3) : 0u);
                    orow[g * 4 + j] = f;
                }
            }
        }
        __syncthreads();   // smem reuse safety for grid-stride iterations
    }
}

extern "C" void kernel_launch(void* const* d_in, const int* in_sizes, int n_in,
                              void* d_out, int out_size)
{
    const int* x = (const int*)d_in[0];
    float* out = (float*)d_out;
    // K = 2048 for this problem; out_size is the output ELEMENT count.
    const int rows = out_size / 2048;
    int blocks = (rows + RPB - 1) / RPB;
    if (blocks < 1) blocks = 1;
    ita_softmax_kernel<<<blocks, 256>>>(x, out, rows);
}

// round 12
// speedup vs baseline: 1.3719x; 1.3719x over previous
#include <cuda_runtime.h>
#include <cstdint>

// ITA integer softmax (WIDTH=16, BITS=8, EPS_MAX=1.0 -> exact integer shifts).
// Output dtype: float32 (confirmed R8).
//
// One warp = one row (K=2048 = 128 groups of 16); lane l owns groups 32k+l.
// Register-compressed: per group keep cmax (int) + 4 packed-byte words of
// (cmax - v); raw values are never held across barriers.
//
// Phase A (per warp, per k-chunk, serialized by shfl carry):
//   load 16 vals -> cmax, pack bytes, warp prefix-max (+carry) -> pm,
//   s = pm - prev, t = sum(256 >> (pm - v)), store (min(s,31)<<13)|t to smem.
// Phase B (warp 0, 8 lanes SIMD): serial 128-step scan e=(e>>s)+t,
//   inv = 65280/e.
// Phase C: out = float(inv >> min((gmax - cmax_k) + b, 31)), float4 stores.

#define FULL_MASK 0xFFFFFFFFu
#define RPB 8           // rows per block (8 warps)
#define GPAD 132        // 128 + 4 pad -> 8 scan lanes stride 132: conflict-free

__global__ __launch_bounds__(256, 4)
void ita_softmax_kernel(const int* __restrict__ x,
                        float* __restrict__ out,
                        int rows)
{
    const int warp = threadIdx.x >> 5;
    const int lane = threadIdx.x & 31;

    __shared__ int sw[RPB][GPAD];
    __shared__ int s_inv[RPB];

    for (int row0 = blockIdx.x * RPB; row0 < rows; row0 += gridDim.x * RPB) {
        const int row = row0 + warp;
        const bool valid = (row < rows);   // uniform per warp

        unsigned packed[4][4];   // (cmax - v) bytes, 16 elems per group
        int cmax[4];
        int carry = -128;        // running prefix max entering current chunk

        // ---- Phase A: load + per-group max + prefix-max + t, all fused ----
        if (valid) {
            const int4* xrow = reinterpret_cast<const int4*>(x) + (size_t)row * 512;
            #pragma unroll 1
            for (int k = 0; k < 4; k++) {
                const int g = k * 32 + lane;      // group index 0..127
                int v[16];
                #pragma unroll
                for (int j = 0; j < 4; j++) {
                    int4 t4 = xrow[g * 4 + j];
                    v[j*4+0] = t4.x; v[j*4+1] = t4.y;
                    v[j*4+2] = t4.z; v[j*4+3] = t4.w;
                }
                int cm = v[0];
                #pragma unroll
                for (int j = 1; j < 16; j++) cm = max(cm, v[j]);
                cmax[k] = cm;

                #pragma unroll
                for (int j = 0; j < 4; j++) {
                    packed[k][j] = (unsigned)(cm - v[j*4+0])
                                 | ((unsigned)(cm - v[j*4+1]) << 8)
                                 | ((unsigned)(cm - v[j*4+2]) << 16)
                                 | ((unsigned)(cm - v[j*4+3]) << 24);
                }

                // inclusive prefix max over lanes (= groups in order)
                int pm = cm;
                #pragma unroll
                for (int d = 1; d < 32; d <<= 1) {
                    int o = __shfl_up_sync(FULL_MASK, pm, d);
                    if (lane >= d) pm = max(pm, o);
                }
                pm = max(pm, carry);

                int prev = __shfl_up_sync(FULL_MASK, pm, 1);
                if (lane == 0) prev = carry;
                int s = pm - prev;                      // >= 0
                carry = __shfl_sync(FULL_MASK, pm, 31); // broadcast chunk max

                int t = 0;
                #pragma unroll
                for (int j = 0; j < 16; j++) {
                    int d = pm - v[j];                 // >= 0
                    t += (d < 9) ? (256 >> d) : 0;     // d>=9 contributes 0
                }
                // t <= 4096 fits 13 bits; s clamped to 31 (e < 2^20, so
                // e>>31 == 0 == reference's s>=32 behavior)
                sw[warp][g] = (min(s, 31) << 13) | t;
            }
        }
        __syncthreads();

        // ---- Phase B: serial eps scan + reciprocal (8 rows SIMD) ----
        if (warp == 0 && lane < RPB && (row0 + lane) < rows) {
            const int* p = sw[lane];
            int e = 0;
            #pragma unroll 8
            for (int g = 0; g < 128; g++) {
                int w = p[g];
                e = (e >> (w >> 13)) + (w & 0x1FFF);
            }
            s_inv[lane] = 65280 / e;                   // e >= 256 always
        }
        __syncthreads();

        // ---- Phase C: output as float32 ----
        if (valid) {
            const unsigned inv = (unsigned)s_inv[warp];  // <= 255
            const int gm = carry;                        // final row max
            float4* orow = reinterpret_cast<float4*>(out + (size_t)row * 2048);
            #pragma unroll
            for (int k = 0; k < 4; k++) {
                const int g = k * 32 + lane;
                const int base = gm - cmax[k];           // >= 0
                #pragma unroll
                for (int j = 0; j < 4; j++) {
                    unsigned p = packed[k][j];
                    int d0 = base + (int)(p & 255u);
                    int d1 = base + (int)((p >> 8) & 255u);
                    int d2 = base + (int)((p >> 16) & 255u);
                    int d3 = base + (int)(p >> 24);
                    float4 f;
                    f.x = (float)(inv >> min(d0, 31));
                    f.y = (float)(inv >> min(d1, 31));
                    f.z = (float)(inv >> min(d2, 31));
                    f.w = (float)(inv >> min(d3, 31));
                    orow[g * 4 + j] = f;
                }
            }
        }
        __syncthreads();   // smem reuse safety across grid-stride iterations
    }
}

extern "C" void kernel_launch(void* const* d_in, const int* in_sizes, int n_in,
                              void* d_out, int out_size)
{
    const int* x = (const int*)d_in[0];
    float* out = (float*)d_out;
    const int rows = out_size / 2048;      // K = 2048
    int blocks = (rows + RPB - 1) / RPB;
    if (blocks < 1) blocks = 1;
    ita_softmax_kernel<<<blocks, 256>>>(x, out, rows);
}